// round 16
// baseline (speedup 1.0000x reference)
#include <cuda_runtime.h>
#include <cuda_fp16.h>
#include <cstdint>
#include <math.h>

#define NS   1024
#define SEQ  64
#define EDIM 256
#define HDIM 512
#define GDIM 2048
#define VOC  32000

// ---------------- device scratch ----------------
__device__ __half   g_h16[2][2 * NS * HDIM];     // [parity][dir*NS*H + n*H + k]
__device__ int      g_len [NS];
__device__ __half   g_whh_h[2 * GDIM * HDIM];    // permuted fp16 weights
__device__ __half   g_wih_h[2 * GDIM * EDIM];
__device__ __half   g_emb_h[VOC * EDIM];         // fp16 embedding
__device__ unsigned g_syncg[16 * 32];            // per-(dir,n-tile) counters, 128B apart

// ---------------- helpers ----------------
__device__ __forceinline__ uint32_t smem_u32(const void* ptr) {
    uint32_t a;
    asm("{ .reg .u64 t; cvta.to.shared.u64 t, %1; cvt.u32.u64 %0, t; }" : "=r"(a) : "l"(ptr));
    return a;
}
#define CP_ASYNC16(dst, src) \
    asm volatile("cp.async.cg.shared.global [%0], [%1], 16;" :: "r"(dst), "l"(src) : "memory")
#define CP_COMMIT() asm volatile("cp.async.commit_group;" ::: "memory")
#define CP_WAIT(n)  asm volatile("cp.async.wait_group %0;" :: "n"(n) : "memory")

__device__ __forceinline__ void ldsm4(uint32_t* r, uint32_t addr) {
    asm volatile("ldmatrix.sync.aligned.m8n8.x4.shared.b16 {%0,%1,%2,%3}, [%4];"
        : "=r"(r[0]), "=r"(r[1]), "=r"(r[2]), "=r"(r[3]) : "r"(addr));
}
__device__ __forceinline__ void mma16816(float* c, const uint32_t* a, const uint32_t* b) {
    asm volatile("mma.sync.aligned.m16n8k16.row.col.f32.f16.f16.f32 "
        "{%0,%1,%2,%3}, {%4,%5,%6,%7}, {%8,%9}, {%0,%1,%2,%3};"
        : "+f"(c[0]), "+f"(c[1]), "+f"(c[2]), "+f"(c[3])
        : "r"(a[0]), "r"(a[1]), "r"(a[2]), "r"(a[3]), "r"(b[0]), "r"(b[1]));
}
__device__ __forceinline__ uint32_t pack_hi2(float a, float b) {
    __half2 H = __halves2half2(__float2half_rn(a), __float2half_rn(b));
    return *reinterpret_cast<uint32_t*>(&H);
}
// sigmoid via single MUFU.TANH
__device__ __forceinline__ float sigt(float x) {
    return fmaf(0.5f, __tanhf(0.5f * x), 0.5f);
}

// ---------------- smem layout (bytes) ----------------
// stage: A 128x64B swizzled (8192) | B 128x64B swizzled (8192) = 16384; 4 stages
#define ST_SZ   16384
#define B_OFF   8192
#define NSTG    4
#define SM_C    65536               // float [128][36]  persistent c (32 j + pad)
#define SM_P    83968               // float [128][36]  persistent pool
#define SM_TOK  102400              // int   [2][128]   double-buffered tokens
#define SM_BIAS 103424              // float [128]
#define SM_LEN  103936              // int   [128]
#define SMEM_SZ 104448
#define SM_HS   0                   // __half [128][40] h staging (aliases stage 0)

// ---------------- merged prep ----------------
__global__ void k_prep(const int* __restrict__ docs, const float* __restrict__ emb,
                       const float* __restrict__ wih_f, const float* __restrict__ wih_b,
                       const float* __restrict__ whh_f, const float* __restrict__ whh_b)
{
    int blk = blockIdx.x;
    if (blk < 4096) {
        int idx = blk * 256 + threadIdx.x;             // 1048576
        g_h16[0][idx] = __float2half(0.f);
        if (idx < NS) {
            int cnt = 0;
            #pragma unroll
            for (int t = 0; t < SEQ; t++) cnt += (docs[idx * SEQ + t] != 0);
            g_len[idx] = cnt;
        }
        if (idx < 16 * 32) g_syncg[idx] = 0u;
    } else if (blk < 12096) {
        int idx = (blk - 4096) * 256 + threadIdx.x;    // 2048000
        float4 v = ((const float4*)emb)[idx];
        ((uint2*)g_emb_h)[idx] = make_uint2(pack_hi2(v.x, v.y), pack_hi2(v.z, v.w));
    } else if (blk < 13120) {
        int idx = (blk - 12096) * 256 + threadIdx.x;   // 262144
        int k4 = idx & 63, p = (idx >> 6) & 2047, dir = idx >> 17;
        const float* W = dir ? wih_b : wih_f;
        float4 v = *(const float4*)(W + (size_t)((p & 3) * HDIM + (p >> 2)) * EDIM + k4 * 4);
        *(uint2*)(g_wih_h + (size_t)(dir * GDIM + p) * EDIM + k4 * 4) =
            make_uint2(pack_hi2(v.x, v.y), pack_hi2(v.z, v.w));
    } else {
        int idx = (blk - 13120) * 256 + threadIdx.x;   // 524288
        int k4 = idx & 127, p = (idx >> 7) & 2047, dir = idx >> 18;
        const float* W = dir ? whh_b : whh_f;
        float4 v = *(const float4*)(W + (size_t)((p & 3) * HDIM + (p >> 2)) * HDIM + k4 * 4);
        *(uint2*)(g_whh_h + (size_t)(dir * GDIM + p) * HDIM + k4 * 4) =
            make_uint2(pack_hi2(v.x, v.y), pack_hi2(v.z, v.w));
    }
}

// ---------------- persistent step kernel ----------------
// grid (16,8,2) = 256 CTAs, 2/SM. CTA: M=128 (n), N=128 (gates), K=768 (24 chunks).
// 128 threads, 4 warps (2 mw x 2 nw), warp tile 64x64. Two CTAs per SM overlap
// each other's epilogue/sync/x-segment with window-loop mma work.
__global__ void __launch_bounds__(128, 2) k_persist(
    const int* __restrict__ docs, const int* __restrict__ doc_lens,
    const float* __restrict__ b_f, const float* __restrict__ b_b,
    float* __restrict__ out)
{
    extern __shared__ char smem[];
    const uint32_t sb = smem_u32(smem);
    const int tid = threadIdx.x;
    const int dir = blockIdx.z;
    const int by  = blockIdx.y;
    const int n0  = by * 128;
    const int p0  = blockIdx.x * 128;

    int*    tokS  = (int*)(smem + SM_TOK);    // [2][128]
    float*  biasS = (float*)(smem + SM_BIAS);
    int*    lenS  = (int*)(smem + SM_LEN);
    float*  cS    = (float*)(smem + SM_C);    // [128][36]
    float*  pS    = (float*)(smem + SM_P);    // [128][36]
    __half* hS    = (__half*)(smem + SM_HS);  // [128][40]

    const __half* __restrict__ WHH = g_whh_h + (size_t)(dir * GDIM + p0) * HDIM;
    const __half* __restrict__ WIH = g_wih_h + (size_t)(dir * GDIM + p0) * EDIM;
    const float*  __restrict__ bias = dir ? b_b : b_f;
    const int j0 = p0 >> 2;                   // 32 j-columns per CTA
    unsigned* syncp = &g_syncg[(dir * 8 + by) * 32];

    if (tid < 128) lenS[tid] = g_len[n0 + tid];
    { int p = p0 + tid; biasS[tid] = bias[(p & 3) * HDIM + (p >> 2)]; }
    #pragma unroll 4
    for (int i = tid; i < 2 * 128 * 36; i += 128) cS[i] = 0.f;   // zeros cS + pS (contiguous)

    const int lane = tid & 31, w = tid >> 5;
    const int mw = w & 1, nw = w >> 1;
    // swizzled ldsm addressing (64B rows, kc ^= (row>>1)&3)
    const uint32_t aBase = (uint32_t)(mw * 64 + (lane & 15)) * 64;
    const uint32_t aX    = ((lane & 15) >> 1) & 3;
    const uint32_t axk0  = (((lane >> 4) ^ aX) << 4);
    const uint32_t axk1  = (((2 + (lane >> 4)) ^ aX) << 4);
    const uint32_t bBase = B_OFF + (uint32_t)(nw * 64 + (lane & 7) + ((lane >> 4) << 3)) * 64;
    const uint32_t bX    = ((lane & 7) >> 1) & 3;
    const uint32_t bxk0  = ((((lane >> 3) & 1) ^ bX) << 4);
    const uint32_t bxk1  = (((2 + ((lane >> 3) & 1)) ^ bX) << 4);
    const int qr = lane >> 2, c2 = (lane & 3) * 2, odd = lane & 1;

    __syncthreads();
    float bias0[8], bias1[8];
    #pragma unroll
    for (int nf = 0; nf < 8; nf++) {
        int pc = nw * 64 + nf * 8 + c2;
        bias0[nf] = biasS[pc];
        bias1[nf] = biasS[pc + 1];
    }

    float C[4][8][4];

    // fill x chunk ch (0-7): emb gather + W_ih  (A: 512 16B slots, B: 512)
    auto fill_x = [&](int ch, const int* tok) {
        uint32_t base = sb + (uint32_t)(ch % NSTG) * ST_SZ;
        const int k0 = ch * 32;
        #pragma unroll
        for (int i = 0; i < 4; i++) {
            int s = tid + i * 128;
            int r = s >> 2, kc = s & 3;
            uint32_t d = base + r * 64 + ((kc ^ ((r >> 1) & 3)) << 4);
            CP_ASYNC16(d, g_emb_h + (size_t)tok[r] * EDIM + k0 + kc * 8);
        }
        #pragma unroll
        for (int i = 0; i < 4; i++) {
            int s = tid + i * 128;
            int row = s >> 2, kc = s & 3;
            uint32_t d = base + B_OFF + row * 64 + ((kc ^ ((row >> 1) & 3)) << 4);
            CP_ASYNC16(d, WIH + (size_t)row * EDIM + k0 + kc * 8);
        }
    };
    // fill h chunk ch (8-23): h + W_hh
    auto fill_h = [&](int ch, const __half* Hc) {
        uint32_t base = sb + (uint32_t)(ch % NSTG) * ST_SZ;
        const int k0 = (ch - 8) * 32;
        #pragma unroll
        for (int i = 0; i < 4; i++) {
            int s = tid + i * 128;
            int r = s >> 2, kc = s & 3;
            uint32_t d = base + r * 64 + ((kc ^ ((r >> 1) & 3)) << 4);
            CP_ASYNC16(d, Hc + r * HDIM + k0 + kc * 8);
        }
        #pragma unroll
        for (int i = 0; i < 4; i++) {
            int s = tid + i * 128;
            int row = s >> 2, kc = s & 3;
            uint32_t d = base + B_OFF + row * 64 + ((kc ^ ((row >> 1) & 3)) << 4);
            CP_ASYNC16(d, WHH + (size_t)row * HDIM + k0 + kc * 8);
        }
    };

    auto compute_chunk = [&](uint32_t st) {
        #pragma unroll
        for (int kk = 0; kk < 2; kk++) {
            const uint32_t ax = kk ? axk1 : axk0;
            const uint32_t bx = kk ? bxk1 : bxk0;
            uint32_t Ah[4][4], Bh[4][4];
            #pragma unroll
            for (int mf = 0; mf < 4; mf++) ldsm4(Ah[mf], st + aBase + mf * 1024 + ax);
            #pragma unroll
            for (int nq = 0; nq < 4; nq++) ldsm4(Bh[nq], st + bBase + nq * 1024 + bx);
            #pragma unroll
            for (int mf = 0; mf < 4; mf++)
                #pragma unroll
                for (int nf = 0; nf < 8; nf++)
                    mma16816(C[mf][nf], Ah[mf], &Bh[nf >> 1][(nf & 1) * 2]);
        }
    };

    auto zeroC = [&]() {
        #pragma unroll
        for (int a = 0; a < 4; a++)
            #pragma unroll
            for (int b = 0; b < 8; b++)
                #pragma unroll
                for (int q = 0; q < 4; q++) C[a][b][q] = 0.f;
    };

    // x-segment (runs in the sync shadow): computes pairs 0,1 (chunks 0-3),
    // leaves pair2 (chunks 4,5) pending. Depth-1 fill-after-barrier schedule.
    // Entry: no pending groups; all threads past a barrier after hS/stage readers.
    auto x_segment = [&](const int* tok) {
        fill_x(0, tok); fill_x(1, tok); CP_COMMIT();     // stages 0,1
        CP_WAIT(0);
        __syncthreads();
        fill_x(2, tok); fill_x(3, tok); CP_COMMIT();     // stages 2,3
        compute_chunk(sb + 0 * ST_SZ);
        compute_chunk(sb + 1 * ST_SZ);
        CP_WAIT(0);
        __syncthreads();
        fill_x(4, tok); fill_x(5, tok); CP_COMMIT();     // stages 0,1 (readers passed barrier)
        compute_chunk(sb + 2 * ST_SZ);
        compute_chunk(sb + 3 * ST_SZ);
        // exit: pair2 (chunks 4,5) pending
    };

    // bootstrap: tokens for step 0, x-segment (h parity 0 zeroed by prep)
    {
        const int u0 = dir ? (SEQ - 1) : 0;
        if (tid < 128) tokS[tid] = docs[(n0 + tid) * SEQ + u0];
        __syncthreads();
        zeroC();
        x_segment(tokS);
    }

    #pragma unroll 1
    for (int step = 0; step < SEQ; step++) {
        const int u = dir ? (SEQ - 1 - step) : step;
        const __half* __restrict__ H0 = g_h16[step & 1] + (size_t)dir * NS * HDIM + (size_t)n0 * HDIM;
        const int* tokC = tokS + (step & 1) * 128;

        // windows p=2..11: WAIT(0) -> barrier -> fill(pair p+1) -> compute(pair p)
        // fill targets stages (2p+2)%4, disjoint from compute stages (2p)%4,(2p+1)%4;
        // all prior readers of the fill target passed this window's barrier.
        #pragma unroll 1
        for (int p = 2; p < 12; p++) {
            CP_WAIT(0);
            __syncthreads();
            if (p < 11) {
                int ch0 = 2 * p + 2, ch1 = 2 * p + 3;
                if (ch0 < 8) { fill_x(ch0, tokC); } else { fill_h(ch0, H0); }
                if (ch1 < 8) { fill_x(ch1, tokC); } else { fill_h(ch1, H0); }
                CP_COMMIT();
            }
            compute_chunk(sb + (uint32_t)((2 * p)     % NSTG) * ST_SZ);
            compute_chunk(sb + (uint32_t)((2 * p + 1) % NSTG) * ST_SZ);
        }

        // ---- epilogue phase A: gates -> c/pool (smem), h -> hS (fp16) ----
        // hS aliases stage 0; last readers (pair 10, stages 0,1) passed barrier at p=11.
        #pragma unroll
        for (int mf = 0; mf < 4; mf++) {
            const int rl = mw * 64 + mf * 16 + qr + odd * 8;   // own row
            const bool inlen = (u < lenS[rl]);
            #pragma unroll
            for (int nf = 0; nf < 8; nf++) {
                float y00 = C[mf][nf][0] + bias0[nf];   // rh0
                float y01 = C[mf][nf][1] + bias1[nf];
                float y10 = C[mf][nf][2] + bias0[nf];   // rh1
                float y11 = C[mf][nf][3] + bias1[nf];
                float s00 = __shfl_xor_sync(0xffffffffu, y00, 1);
                float s01 = __shfl_xor_sync(0xffffffffu, y01, 1);
                float s10 = __shfl_xor_sync(0xffffffffu, y10, 1);
                float s11 = __shfl_xor_sync(0xffffffffu, y11, 1);
                float yi = odd ? s10 : y00;
                float yf = odd ? s11 : y01;
                float yg = odd ? y10 : s00;
                float yo = odd ? y11 : s01;
                float si = sigt(yi);
                float sf = sigt(yf);
                float so = sigt(yo);
                float tg = __tanhf(yg);
                int jl = (nw * 64 + nf * 8 + (c2 & 4)) >> 2;
                float c = sf * cS[rl * 36 + jl] + si * tg;
                float h = so * __tanhf(c);
                cS[rl * 36 + jl] = c;
                if (inlen) pS[rl * 36 + jl] += h;
                hS[rl * 40 + jl] = __float2half_rn(h);
            }
        }
        zeroC();
        __syncthreads();

        // ---- epilogue phase B: coalesced uint4 h copy + next-step tokens ----
        __half* __restrict__ NH = g_h16[(step + 1) & 1] + (size_t)dir * NS * HDIM;
        #pragma unroll
        for (int i = 0; i < 4; i++) {
            int idx = tid + i * 128;                  // 512 slots of 8 halves (32 j per row)
            int r = idx >> 2, q = idx & 3;
            *(uint4*)&NH[(size_t)(n0 + r) * HDIM + j0 + q * 8] = *(uint4*)&hS[r * 40 + q * 8];
        }
        if (step + 1 < SEQ && tid < 128) {
            const int un = dir ? (SEQ - 2 - step) : (step + 1);
            tokS[((step + 1) & 1) * 128 + tid] = docs[(n0 + tid) * SEQ + un];
        }
        __syncthreads();   // hS reads + h stores + token writes complete

        if (step + 1 < SEQ) {
            // release: h of this step is globally visible
            if (tid == 0) {
                __threadfence();
                atomicAdd(syncp, 1u);
            }
            // overlap the sync window with next step's x-projection compute
            x_segment(tokS + ((step + 1) & 1) * 128);
            // spin for the 16-CTA group, then barrier before h-chunk fills
            if (tid == 0) {
                unsigned target = 16u * (unsigned)(step + 1);
                while (*(volatile unsigned*)syncp < target) __nanosleep(32);
                __threadfence();
            }
            __syncthreads();
        }
    }

    // ---- final: pool/len, doc mask, write out slice (32 j per CTA) ----
    #pragma unroll 1
    for (int i = tid; i < 128 * 8; i += 128) {
        int r = i >> 3, q = i & 7;
        int nd = n0 + r;
        int b = nd >> 5, d = nd & 31;
        float4 v = make_float4(0.f, 0.f, 0.f, 0.f);
        if (d < doc_lens[b]) {
            int len = lenS[r];
            float inv = 1.f / (float)(len > 0 ? len : 1);
            float4 pv = *(float4*)&pS[r * 36 + q * 4];
            v = make_float4(pv.x * inv, pv.y * inv, pv.z * inv, pv.w * inv);
        }
        *(float4*)&out[(size_t)nd * 1024 + dir * 512 + j0 + q * 4] = v;
    }
}

extern "C" void kernel_launch(void* const* d_in, const int* in_sizes, int n_in,
                              void* d_out, int out_size)
{
    const int* docs     = (const int*)d_in[0];
    const int* doc_lens = (const int*)d_in[1];
    int base = (n_in >= 10 && in_sizes[2] == 1) ? 3 : 2;
    const float* emb   = (const float*)d_in[base + 0];
    const float* wih_f = (const float*)d_in[base + 1];
    const float* whh_f = (const float*)d_in[base + 2];
    const float* b_f   = (const float*)d_in[base + 3];
    const float* wih_b = (const float*)d_in[base + 4];
    const float* whh_b = (const float*)d_in[base + 5];
    const float* b_b   = (const float*)d_in[base + 6];
    float* out = (float*)d_out;

    cudaFuncSetAttribute(k_persist, cudaFuncAttributeMaxDynamicSharedMemorySize, SMEM_SZ);

    k_prep   <<<15168, 256>>>(docs, emb, wih_f, wih_b, whh_f, whh_b);
    k_persist<<<dim3(16, 8, 2), 128, SMEM_SZ>>>(docs, doc_lens, b_f, b_b, out);
}

// round 17
// speedup vs baseline: 1.1324x; 1.1324x over previous
#include <cuda_runtime.h>
#include <cuda_fp16.h>
#include <cstdint>
#include <math.h>

#define NS   1024
#define SEQ  64
#define EDIM 256
#define HDIM 512
#define GDIM 2048
#define VOC  32000

// ---------------- device scratch ----------------
__device__ __half   g_h16[2][2 * NS * HDIM];     // [parity][dir*NS*H + n*H + k]
__device__ int      g_len [NS];
__device__ __half   g_whh_h[2 * GDIM * HDIM];    // permuted fp16 weights
__device__ __half   g_wih_h[2 * GDIM * EDIM];
__device__ __half   g_emb_h[VOC * EDIM];         // fp16 embedding
__device__ unsigned g_syncg[16 * 32];            // per-(dir,n-tile) counters, 128B apart

// ---------------- helpers ----------------
__device__ __forceinline__ uint32_t smem_u32(const void* ptr) {
    uint32_t a;
    asm("{ .reg .u64 t; cvta.to.shared.u64 t, %1; cvt.u32.u64 %0, t; }" : "=r"(a) : "l"(ptr));
    return a;
}
#define CP_ASYNC16(dst, src) \
    asm volatile("cp.async.cg.shared.global [%0], [%1], 16;" :: "r"(dst), "l"(src) : "memory")
#define CP_COMMIT() asm volatile("cp.async.commit_group;" ::: "memory")
#define CP_WAIT(n)  asm volatile("cp.async.wait_group %0;" :: "n"(n) : "memory")

__device__ __forceinline__ void ldsm4(uint32_t* r, uint32_t addr) {
    asm volatile("ldmatrix.sync.aligned.m8n8.x4.shared.b16 {%0,%1,%2,%3}, [%4];"
        : "=r"(r[0]), "=r"(r[1]), "=r"(r[2]), "=r"(r[3]) : "r"(addr));
}
__device__ __forceinline__ void mma16816(float* c, const uint32_t* a, const uint32_t* b) {
    asm volatile("mma.sync.aligned.m16n8k16.row.col.f32.f16.f16.f32 "
        "{%0,%1,%2,%3}, {%4,%5,%6,%7}, {%8,%9}, {%0,%1,%2,%3};"
        : "+f"(c[0]), "+f"(c[1]), "+f"(c[2]), "+f"(c[3])
        : "r"(a[0]), "r"(a[1]), "r"(a[2]), "r"(a[3]), "r"(b[0]), "r"(b[1]));
}
__device__ __forceinline__ uint32_t pack_hi2(float a, float b) {
    __half2 H = __halves2half2(__float2half_rn(a), __float2half_rn(b));
    return *reinterpret_cast<uint32_t*>(&H);
}
// sigmoid via single MUFU.TANH
__device__ __forceinline__ float sigt(float x) {
    return fmaf(0.5f, __tanhf(0.5f * x), 0.5f);
}

// ---------------- smem layout (bytes) ----------------
// stage: A 128x64B swizzled (8192) | B 256x64B swizzled (16384) = 24576; 6 stages
#define ST_SZ   24576
#define B_OFF   8192
#define NSTG    6
#define SM_C    147456              // float [128][68]  persistent c
#define SM_P    182272              // float [128][68]  persistent pool
#define SM_TOK  217088              // int   [2][128]   double-buffered tokens
#define SM_BIAS 218112              // float [256]
#define SM_LEN  219136              // int   [128]
#define SMEM_SZ 219648
#define SM_HS   0                   // __half [128][72] h staging (aliases stages 0-1)

// ---------------- merged prep ----------------
__global__ void k_prep(const int* __restrict__ docs, const float* __restrict__ emb,
                       const float* __restrict__ wih_f, const float* __restrict__ wih_b,
                       const float* __restrict__ whh_f, const float* __restrict__ whh_b)
{
    int blk = blockIdx.x;
    if (blk < 4096) {
        int idx = blk * 256 + threadIdx.x;             // 1048576
        g_h16[0][idx] = __float2half(0.f);
        if (idx < NS) {
            int cnt = 0;
            #pragma unroll
            for (int t = 0; t < SEQ; t++) cnt += (docs[idx * SEQ + t] != 0);
            g_len[idx] = cnt;
        }
        if (idx < 16 * 32) g_syncg[idx] = 0u;
    } else if (blk < 12096) {
        int idx = (blk - 4096) * 256 + threadIdx.x;    // 2048000
        float4 v = ((const float4*)emb)[idx];
        ((uint2*)g_emb_h)[idx] = make_uint2(pack_hi2(v.x, v.y), pack_hi2(v.z, v.w));
    } else if (blk < 13120) {
        int idx = (blk - 12096) * 256 + threadIdx.x;   // 262144
        int k4 = idx & 63, p = (idx >> 6) & 2047, dir = idx >> 17;
        const float* W = dir ? wih_b : wih_f;
        float4 v = *(const float4*)(W + (size_t)((p & 3) * HDIM + (p >> 2)) * EDIM + k4 * 4);
        *(uint2*)(g_wih_h + (size_t)(dir * GDIM + p) * EDIM + k4 * 4) =
            make_uint2(pack_hi2(v.x, v.y), pack_hi2(v.z, v.w));
    } else {
        int idx = (blk - 13120) * 256 + threadIdx.x;   // 524288
        int k4 = idx & 127, p = (idx >> 7) & 2047, dir = idx >> 18;
        const float* W = dir ? whh_b : whh_f;
        float4 v = *(const float4*)(W + (size_t)((p & 3) * HDIM + (p >> 2)) * HDIM + k4 * 4);
        *(uint2*)(g_whh_h + (size_t)(dir * GDIM + p) * HDIM + k4 * 4) =
            make_uint2(pack_hi2(v.x, v.y), pack_hi2(v.z, v.w));
    }
}

// ---------------- persistent step kernel ----------------
// grid (8,8,2) = 128 CTAs (1/SM). CTA: M=128 (n), N=256 (gates p=4j+g), K=768.
// 256 threads, 8 warps (2 mw x 4 nw), warp tile 64x64. x-projection chunks of
// step s+1 computed inside the group-sync window. Fills interleaved between computes.
__global__ void __launch_bounds__(256, 1) k_persist(
    const int* __restrict__ docs, const int* __restrict__ doc_lens,
    const float* __restrict__ b_f, const float* __restrict__ b_b,
    float* __restrict__ out)
{
    extern __shared__ char smem[];
    const uint32_t sb = smem_u32(smem);
    const int tid = threadIdx.x;
    const int dir = blockIdx.z;
    const int by  = blockIdx.y;
    const int n0  = by * 128;
    const int p0  = blockIdx.x * 256;

    int*    tokS  = (int*)(smem + SM_TOK);    // [2][128]
    float*  biasS = (float*)(smem + SM_BIAS);
    int*    lenS  = (int*)(smem + SM_LEN);
    float*  cS    = (float*)(smem + SM_C);
    float*  pS    = (float*)(smem + SM_P);
    __half* hS    = (__half*)(smem + SM_HS);  // [128][72]

    const __half* __restrict__ WHH = g_whh_h + (size_t)(dir * GDIM + p0) * HDIM;
    const __half* __restrict__ WIH = g_wih_h + (size_t)(dir * GDIM + p0) * EDIM;
    const float*  __restrict__ bias = dir ? b_b : b_f;
    const int j0 = p0 >> 2;
    unsigned* syncp = &g_syncg[(dir * 8 + by) * 32];

    if (tid < 128) lenS[tid] = g_len[n0 + tid];
    { int p = p0 + tid; biasS[tid] = bias[(p & 3) * HDIM + (p >> 2)]; }
    #pragma unroll 4
    for (int i = tid; i < 2 * 128 * 68; i += 256) cS[i] = 0.f;   // zeros cS + pS (contiguous)

    const int lane = tid & 31, w = tid >> 5;
    const int mw = w & 1, nw = w >> 1;
    // swizzled ldsm addressing (64B rows, kc ^= (row>>1)&3)
    const uint32_t aBase = (uint32_t)(mw * 64 + (lane & 15)) * 64;
    const uint32_t aX    = ((lane & 15) >> 1) & 3;
    const uint32_t axk0  = (((lane >> 4) ^ aX) << 4);
    const uint32_t axk1  = (((2 + (lane >> 4)) ^ aX) << 4);
    const uint32_t bBase = B_OFF + (uint32_t)(nw * 64 + (lane & 7) + ((lane >> 4) << 3)) * 64;
    const uint32_t bX    = ((lane & 7) >> 1) & 3;
    const uint32_t bxk0  = ((((lane >> 3) & 1) ^ bX) << 4);
    const uint32_t bxk1  = (((2 + ((lane >> 3) & 1)) ^ bX) << 4);
    const int qr = lane >> 2, c2 = (lane & 3) * 2, odd = lane & 1;

    __syncthreads();
    float bias0[8], bias1[8];
    #pragma unroll
    for (int nf = 0; nf < 8; nf++) {
        int pc = nw * 64 + nf * 8 + c2;
        bias0[nf] = biasS[pc];
        bias1[nf] = biasS[pc + 1];
    }

    float C[4][8][4];

    // fill x chunk ch (0-7): emb gather + W_ih
    auto fill_x = [&](int ch, const int* tok) {
        uint32_t base = sb + (uint32_t)(ch % NSTG) * ST_SZ;
        const int k0 = ch * 32;
        #pragma unroll
        for (int i = 0; i < 2; i++) {            // A: 512 slots
            int s = tid + i * 256;
            int r = s >> 2, kc = s & 3;
            uint32_t d = base + r * 64 + ((kc ^ ((r >> 1) & 3)) << 4);
            CP_ASYNC16(d, g_emb_h + (size_t)tok[r] * EDIM + k0 + kc * 8);
        }
        #pragma unroll
        for (int i = 0; i < 4; i++) {            // B: 1024 slots
            int s = tid + i * 256;
            int row = s >> 2, kc = s & 3;
            uint32_t d = base + B_OFF + row * 64 + ((kc ^ ((row >> 1) & 3)) << 4);
            CP_ASYNC16(d, WIH + (size_t)row * EDIM + k0 + kc * 8);
        }
    };
    // fill h chunk ch (8-23): h + W_hh
    auto fill_h = [&](int ch, const __half* Hc) {
        uint32_t base = sb + (uint32_t)(ch % NSTG) * ST_SZ;
        const int k0 = (ch - 8) * 32;
        #pragma unroll
        for (int i = 0; i < 2; i++) {
            int s = tid + i * 256;
            int r = s >> 2, kc = s & 3;
            uint32_t d = base + r * 64 + ((kc ^ ((r >> 1) & 3)) << 4);
            CP_ASYNC16(d, Hc + r * HDIM + k0 + kc * 8);
        }
        #pragma unroll
        for (int i = 0; i < 4; i++) {
            int s = tid + i * 256;
            int row = s >> 2, kc = s & 3;
            uint32_t d = base + B_OFF + row * 64 + ((kc ^ ((row >> 1) & 3)) << 4);
            CP_ASYNC16(d, WHH + (size_t)row * HDIM + k0 + kc * 8);
        }
    };

    auto compute_chunk = [&](uint32_t st) {
        #pragma unroll
        for (int kk = 0; kk < 2; kk++) {
            const uint32_t ax = kk ? axk1 : axk0;
            const uint32_t bx = kk ? bxk1 : bxk0;
            uint32_t Ah[4][4], Bh[4][4];
            #pragma unroll
            for (int mf = 0; mf < 4; mf++) ldsm4(Ah[mf], st + aBase + mf * 1024 + ax);
            #pragma unroll
            for (int nq = 0; nq < 4; nq++) ldsm4(Bh[nq], st + bBase + nq * 1024 + bx);
            #pragma unroll
            for (int mf = 0; mf < 4; mf++)
                #pragma unroll
                for (int nf = 0; nf < 8; nf++)
                    mma16816(C[mf][nf], Ah[mf], &Bh[nf >> 1][(nf & 1) * 2]);
        }
    };

    auto zeroC = [&]() {
        #pragma unroll
        for (int a = 0; a < 4; a++)
            #pragma unroll
            for (int b = 0; b < 8; b++)
                #pragma unroll
                for (int q = 0; q < 4; q++) C[a][b][q] = 0.f;
    };

    // x-segment: fill chunks 0-3, compute pairs 0-1 (fills interleaved), fill 4-7.
    auto x_segment = [&](const int* tok) {
        fill_x(0, tok); fill_x(1, tok); CP_COMMIT();
        fill_x(2, tok); fill_x(3, tok); CP_COMMIT();
        CP_WAIT(1);
        __syncthreads();
        compute_chunk(sb + 0 * ST_SZ);
        fill_x(4, tok);
        compute_chunk(sb + 1 * ST_SZ);
        fill_x(5, tok); CP_COMMIT();
        CP_WAIT(1);
        __syncthreads();
        compute_chunk(sb + 2 * ST_SZ);
        fill_x(6, tok);
        compute_chunk(sb + 3 * ST_SZ);
        fill_x(7, tok); CP_COMMIT();
        // pending groups: G(4,5), G(6,7)
    };

    // bootstrap: tokens for step 0, x-segment (h parity 0 is zeroed by prep)
    {
        const int u0 = dir ? (SEQ - 1) : 0;
        if (tid < 128) tokS[tid] = docs[(n0 + tid) * SEQ + u0];
        __syncthreads();
        zeroC();
        x_segment(tokS);
    }

    #pragma unroll 1
    for (int step = 0; step < SEQ; step++) {
        const int u = dir ? (SEQ - 1 - step) : step;
        const __half* __restrict__ H0 = g_h16[step & 1] + (size_t)dir * NS * HDIM + (size_t)n0 * HDIM;

        // windows p=2..11: wait -> barrier -> compute(2p) -> fill(2p+4) -> compute(2p+1) -> fill(2p+5)
        #pragma unroll 1
        for (int p = 2; p < 12; p++) {
            if (p < 11) { CP_WAIT(1); } else { CP_WAIT(0); }
            __syncthreads();
            compute_chunk(sb + (uint32_t)((2 * p) % NSTG) * ST_SZ);
            if (p < 10) fill_h(2 * p + 4, H0);
            compute_chunk(sb + (uint32_t)((2 * p + 1) % NSTG) * ST_SZ);
            if (p < 10) { fill_h(2 * p + 5, H0); CP_COMMIT(); }
        }

        // next-step token prefetch (independent smem slot; ordered by epiB barrier)
        if (step + 1 < SEQ && tid < 128) {
            const int un = dir ? (SEQ - 2 - step) : (step + 1);
            tokS[((step + 1) & 1) * 128 + tid] = docs[(n0 + tid) * SEQ + un];
        }

        // ---- epilogue phase A: gates -> c/pool (smem), h -> hS (fp16) ----
        // hS aliases stages 0-1; last read window p=9 (chunks 18,19), all threads
        // passed barriers at p=10,11.
        #pragma unroll
        for (int mf = 0; mf < 4; mf++) {
            const int rl = mw * 64 + mf * 16 + qr + odd * 8;   // own row
            const bool inlen = (u < lenS[rl]);
            #pragma unroll
            for (int nf = 0; nf < 8; nf++) {
                float y00 = C[mf][nf][0] + bias0[nf];   // rh0
                float y01 = C[mf][nf][1] + bias1[nf];
                float y10 = C[mf][nf][2] + bias0[nf];   // rh1
                float y11 = C[mf][nf][3] + bias1[nf];
                float s00 = __shfl_xor_sync(0xffffffffu, y00, 1);
                float s01 = __shfl_xor_sync(0xffffffffu, y01, 1);
                float s10 = __shfl_xor_sync(0xffffffffu, y10, 1);
                float s11 = __shfl_xor_sync(0xffffffffu, y11, 1);
                float yi = odd ? s10 : y00;
                float yf = odd ? s11 : y01;
                float yg = odd ? y10 : s00;
                float yo = odd ? y11 : s01;
                float si = sigt(yi);
                float sf = sigt(yf);
                float so = sigt(yo);
                float tg = __tanhf(yg);
                int jl = (nw * 64 + nf * 8 + (c2 & 4)) >> 2;
                float c = sf * cS[rl * 68 + jl] + si * tg;
                float h = so * __tanhf(c);
                cS[rl * 68 + jl] = c;
                if (inlen) pS[rl * 68 + jl] += h;
                hS[rl * 72 + jl] = __float2half_rn(h);
            }
        }
        zeroC();   // C dead; ready for next step's x-segment
        __syncthreads();

        // ---- epilogue phase B: coalesced uint4 h copy ----
        __half* __restrict__ NH = g_h16[(step + 1) & 1] + (size_t)dir * NS * HDIM;
        #pragma unroll
        for (int i = 0; i < 4; i++) {
            int idx = tid + i * 256;                  // 1024 slots of 8 halves
            int r = idx >> 3, q = idx & 7;
            *(uint4*)&NH[(size_t)(n0 + r) * HDIM + j0 + q * 8] = *(uint4*)&hS[r * 72 + q * 8];
        }
        __syncthreads();   // hS reads + h stores + token writes complete

        if (step + 1 < SEQ) {
            // release: h of this step is globally visible (stores before the barrier)
            if (tid == 0) {
                __threadfence();
                atomicAdd(syncp, 1u);
            }
            // overlap the sync window with next step's x-projection compute
            x_segment(tokS + ((step + 1) & 1) * 128);
            // spin for the 8-CTA group, then barrier before h-chunk fills
            if (tid == 0) {
                unsigned target = 8u * (unsigned)(step + 1);
                while (*(volatile unsigned*)syncp < target) __nanosleep(32);
                __threadfence();
            }
            __syncthreads();
        }
    }

    // ---- final: pool/len, doc mask, write out slice ----
    #pragma unroll 1
    for (int i = tid; i < 128 * 16; i += 256) {
        int r = i >> 4, q = i & 15;
        int nd = n0 + r;
        int b = nd >> 5, d = nd & 31;
        float4 v = make_float4(0.f, 0.f, 0.f, 0.f);
        if (d < doc_lens[b]) {
            int len = lenS[r];
            float inv = 1.f / (float)(len > 0 ? len : 1);
            float4 pv = *(float4*)&pS[r * 68 + q * 4];
            v = make_float4(pv.x * inv, pv.y * inv, pv.z * inv, pv.w * inv);
        }
        *(float4*)&out[(size_t)nd * 1024 + dir * 512 + j0 + q * 4] = v;
    }
}

extern "C" void kernel_launch(void* const* d_in, const int* in_sizes, int n_in,
                              void* d_out, int out_size)
{
    const int* docs     = (const int*)d_in[0];
    const int* doc_lens = (const int*)d_in[1];
    int base = (n_in >= 10 && in_sizes[2] == 1) ? 3 : 2;
    const float* emb   = (const float*)d_in[base + 0];
    const float* wih_f = (const float*)d_in[base + 1];
    const float* whh_f = (const float*)d_in[base + 2];
    const float* b_f   = (const float*)d_in[base + 3];
    const float* wih_b = (const float*)d_in[base + 4];
    const float* whh_b = (const float*)d_in[base + 5];
    const float* b_b   = (const float*)d_in[base + 6];
    float* out = (float*)d_out;

    cudaFuncSetAttribute(k_persist, cudaFuncAttributeMaxDynamicSharedMemorySize, SMEM_SZ);

    k_prep   <<<15168, 256>>>(docs, emb, wih_f, wih_b, whh_f, whh_b);
    k_persist<<<dim3(8, 8, 2), 256, SMEM_SZ>>>(docs, doc_lens, b_f, b_b, out);
}